// round 4
// baseline (speedup 1.0000x reference)
#include <cuda_runtime.h>
#include <math.h>

#define BB 64
#define TT 128
#define DD 256
#define HH 1024
#define NCTA 128
#define NTHR 256
#define CH 64          // k-chunk per pipeline stage (per kw half)
#define A_ST 68        // smem row stride (floats)
// smem ring: 4 stages x 2 kw x (64 A rows + 32 W rows) x A_ST floats
#define RED_OFF 52224  // 4*2*96*68
#define SMEM_FLOATS 54272  // + 2048 red buffer

// ------------------------- device globals -------------------------
__device__ float g_WP1[NCTA * 32 * HH];   // per-CTA P1 slab: 24 Whh0 i/g/o rows + 8 Wout rows (cta<32)
__device__ float g_WP2[NCTA * 24 * DD];   // per-CTA Wih0 i/g/o rows
__device__ float g_WP3[NCTA * 24 * HH];   // per-CTA (Wih1+Whh1) i/g/o rows
__device__ float g_B0[NCTA * 24];         // bih0+bhh0 (i/g/o)
__device__ float g_B1[NCTA * 24];         // bih1+bhh1 (i/g/o)
__device__ float g_h[BB * HH];
__device__ float g_h0[BB * HH];
__device__ float g_imp[BB * DD];
__device__ unsigned g_barcnt;

// ------------------------- helpers -------------------------
__device__ __forceinline__ float to_tf32(float x) {
    float y;
    asm("cvt.rna.tf32.f32 %0, %1;" : "=f"(y) : "f"(x));
    return y;
}
__device__ __forceinline__ void mma_tf32(float* d, const unsigned* a, const unsigned* b) {
    asm volatile(
        "mma.sync.aligned.m16n8k8.row.col.f32.tf32.tf32.f32 "
        "{%0,%1,%2,%3},{%4,%5,%6,%7},{%8,%9},{%0,%1,%2,%3};"
        : "+f"(d[0]), "+f"(d[1]), "+f"(d[2]), "+f"(d[3])
        : "r"(a[0]), "r"(a[1]), "r"(a[2]), "r"(a[3]), "r"(b[0]), "r"(b[1]));
}
__device__ __forceinline__ void cpa16(unsigned s, const float* g) {
    asm volatile("cp.async.cg.shared.global [%0], [%1], 16;" :: "r"(s), "l"(g));
}
__device__ __forceinline__ void cpcommit() { asm volatile("cp.async.commit_group;"); }

__device__ __forceinline__ int As_off(int st, int kw, int row, int k) {
    return (((st * 2 + kw) * 96) + row) * A_ST + k;
}
__device__ __forceinline__ int Ws_off(int st, int kw, int row, int k) {
    return (((st * 2 + kw) * 96) + 64 + row) * A_ST + k;
}

// ------------------------- merged init/pack kernel -------------------------
__device__ __forceinline__ int phys_row(int cta, int r) {  // r in [0,24)
    int u = cta * 8 + (r & 7);
    int g = r >> 3;                       // 0=i,1=g,2=o
    return u + (g == 0 ? 0 : (g == 1 ? 2048 : 3072));
}
#define N1 (NCTA * 32 * HH)
#define N2 (NCTA * 24 * DD)
#define N3 (NCTA * 24 * HH)
#define NBv (NCTA * 24)
#define NHh (BB * HH)

__global__ void pack_all(const float* __restrict__ Wih0, const float* __restrict__ Whh0,
                         const float* __restrict__ bih0, const float* __restrict__ bhh0,
                         const float* __restrict__ Wih1, const float* __restrict__ Whh1,
                         const float* __restrict__ bih1, const float* __restrict__ bhh1,
                         const float* __restrict__ Wout) {
    int idx = blockIdx.x * 256 + threadIdx.x;
    if (idx < N1) {
        int cta = idx >> 15, r = (idx >> 10) & 31, k = idx & 1023;
        float v = 0.0f;
        if (r < 24)        v = Whh0[phys_row(cta, r) * HH + k];
        else if (cta < 32) v = Wout[(cta * 8 + (r - 24)) * HH + k];
        g_WP1[idx] = to_tf32(v);
        return;
    }
    idx -= N1;
    if (idx < N2) {
        int cta = idx / 6144, rem = idx % 6144, r = rem >> 8, k = rem & 255;
        g_WP2[idx] = to_tf32(Wih0[phys_row(cta, r) * DD + k]);
        return;
    }
    idx -= N2;
    if (idx < N3) {
        int cta = idx / 24576, r = (idx >> 10) % 24, k = idx & 1023;
        int p = phys_row(cta, r);
        g_WP3[idx] = to_tf32(Wih1[p * HH + k] + Whh1[p * HH + k]);
        return;
    }
    idx -= N3;
    if (idx < NBv) {
        int p = phys_row(idx / 24, idx % 24);
        g_B0[idx] = bih0[p] + bhh0[p];
        g_B1[idx] = bih1[p] + bhh1[p];
        return;
    }
    idx -= NBv;
    if (idx < NHh) {
        g_h[idx] = 0.0f;
        if (idx == 0) g_barcnt = 0;
    }
}
#define PACK_TOT (N1 + N2 + N3 + NBv + NHh)

// ------------------------- pipeline pieces -------------------------
__device__ __forceinline__ void load_stage(unsigned smb, int st,
        const float* A, int ldA, const float* W, int ldW,
        int khalf, int it, int R, int tid) {
    const int kbase = it * CH;
    #pragma unroll
    for (int i = 0; i < 12; i++) {
        int u = tid + i * NTHR;                 // < 3072
        int kw = (u >= 1536) ? 1 : 0;
        int v  = u - kw * 1536;
        int row = v >> 4, seg = (v & 15) << 2;
        int smoff = (((st * 2 + kw) * 96) + row) * A_ST + seg;
        if (row < 64)
            cpa16(smb + 4u * smoff, A + row * ldA + kw * khalf + kbase + seg);
        else if (row - 64 < R)
            cpa16(smb + 4u * smoff, W + (row - 64) * ldW + kw * khalf + kbase + seg);
    }
    cpcommit();
}

template <int NBLK>
__device__ __forceinline__ void compute_chunk(const float* sm, int st, int kw,
        int m0, int r, int c, float acc[4][4]) {
    #pragma unroll
    for (int s = 0; s < 8; s++) {
        int kb = s * 8;
        unsigned a[4];
        a[0] = __float_as_uint(sm[As_off(st, kw, m0 + r,     kb + c)]);
        a[1] = __float_as_uint(sm[As_off(st, kw, m0 + r + 8, kb + c)]);
        a[2] = __float_as_uint(sm[As_off(st, kw, m0 + r,     kb + c + 4)]);
        a[3] = __float_as_uint(sm[As_off(st, kw, m0 + r + 8, kb + c + 4)]);
        #pragma unroll
        for (int blk = 0; blk < NBLK; blk++) {
            unsigned b[2];
            b[0] = __float_as_uint(sm[Ws_off(st, kw, blk * 8 + r, kb + c)]);
            b[1] = __float_as_uint(sm[Ws_off(st, kw, blk * 8 + r, kb + c + 4)]);
            mma_tf32(acc[blk], a, b);
        }
    }
}

// 4-slot ring, depth-2 prefetch, ONE sync per chunk.
template <int NBLK>
__device__ __forceinline__ void run_phase(unsigned smb, const float* sm,
        const float* A, int ldA, const float* W, int ldW, int khalf, int R,
        float acc[4][4], int tid, int kw, int m0, int r, int c) {
    const int nit = khalf / CH;
    load_stage(smb, 0, A, ldA, W, ldW, khalf, 0, R, tid);
    load_stage(smb, 1, A, ldA, W, ldW, khalf, 1, R, tid);
    for (int it = 0; it < nit; it++) {
        if (it + 2 < nit)
            load_stage(smb, (it + 2) & 3, A, ldA, W, ldW, khalf, it + 2, R, tid);
        else
            cpcommit();
        asm volatile("cp.async.wait_group 2;" ::: "memory");
        __syncthreads();
        compute_chunk<NBLK>(sm, it & 3, kw, m0, r, c, acc);
    }
}

// single-sync cross-kw reduction (adjacent pipeline/barrier syncs fence reuse)
__device__ __forceinline__ void reduce_blocks(float* red, float acc[4][4],
        int kw, int mw, int lane, int b0, int b1) {
    if (kw == 1)
        for (int blk = b0; blk <= b1; blk++)
            #pragma unroll
            for (int q = 0; q < 4; q++)
                red[((mw * 4 + blk) * 32 + lane) * 4 + q] = acc[blk][q];
    __syncthreads();
    if (kw == 0)
        for (int blk = b0; blk <= b1; blk++)
            #pragma unroll
            for (int q = 0; q < 4; q++)
                acc[blk][q] += red[((mw * 4 + blk) * 32 + lane) * 4 + q];
}

__device__ __forceinline__ void gridbar(unsigned* barno) {
    __syncthreads();
    (*barno)++;
    if (threadIdx.x == 0) {
        __threadfence();
        asm volatile("red.relaxed.gpu.global.add.u32 [%0], %1;"
                     :: "l"(&g_barcnt), "r"(1u) : "memory");
        unsigned target = (*barno) * NCTA, v;
        do {
            asm volatile("ld.acquire.gpu.global.u32 %0, [%1];" : "=r"(v) : "l"(&g_barcnt) : "memory");
        } while (v < target);
    }
    __syncthreads();
}

// ------------------------- the persistent kernel -------------------------
__global__ void __launch_bounds__(NTHR, 1) rnn_persist(
        const float* __restrict__ X, const float* __restrict__ Mm,
        const float* __restrict__ bout, float* __restrict__ out) {
    extern __shared__ float sm[];
    unsigned smb = (unsigned)__cvta_generic_to_shared(sm);
    float* red = sm + RED_OFF;
    const int cta = blockIdx.x, tid = threadIdx.x;
    const int warp = tid >> 5, lane = tid & 31;
    const int mw = warp & 3, kw = warp >> 2;
    const int m0 = mw << 4, r = lane >> 2, c = lane & 3;
    const bool has_est = (cta < 32);
    const float* WP1 = g_WP1 + cta * 32 * HH;
    const float* WP2 = g_WP2 + cta * 24 * DD;
    const float* WP3 = g_WP3 + cta * 24 * HH;
    const float* B0p = g_B0 + cta * 24;
    const float* B1p = g_B1 + cta * 24;
    const int u0 = cta * 8;
    unsigned barno = 0;
    float acc[4][4];

    for (int t = 0;; t++) {
        const bool last = (t == TT);
        if (last) {  // h_final -> out tail
            #pragma unroll
            for (int i = tid; i < 512; i += NTHR)
                out[BB * TT * DD + cta * 512 + i] = g_h[cta * 512 + i];
            if (!has_est) break;
        }
        // ---- P1: [gates0 h-part | est] = h @ WP1^T  (k=1024) ----
        #pragma unroll
        for (int blk = 0; blk < 4; blk++)
            #pragma unroll
            for (int q = 0; q < 4; q++) acc[blk][q] = 0.0f;
        if (has_est)
            run_phase<4>(smb, sm, g_h, HH, WP1, HH, 512, 32, acc, tid, kw, m0, r, c);
        else
            run_phase<3>(smb, sm, g_h, HH, WP1, HH, 512, 24, acc, tid, kw, m0, r, c);

        if (has_est) {
            reduce_blocks(red, acc, kw, mw, lane, 3, 3);
            if (kw == 0) {   // est epilogue: write out[t-1], compute imputed
                int d0 = cta * 8;
                #pragma unroll
                for (int half = 0; half < 2; half++) {
                    int b = m0 + r + half * 8;
                    #pragma unroll
                    for (int j = 0; j < 2; j++) {
                        int d = d0 + 2 * c + j;
                        float e = acc[3][half * 2 + j] + bout[d];
                        if (t > 0) out[(b * TT + (t - 1)) * DD + d] = e;
                        if (t < TT) {
                            int xi = (b * TT + t) * DD + d;
                            float m = Mm[xi];
                            g_imp[b * DD + d] = to_tf32(m * X[xi] + (1.0f - m) * e);
                        }
                    }
                }
            }
        }
        if (last) break;
        gridbar(&barno);

        // ---- P2: gates0 += imputed @ WP2^T (k=256), then act0 -> h0 ----
        run_phase<3>(smb, sm, g_imp, DD, WP2, DD, 128, 24, acc, tid, kw, m0, r, c);
        reduce_blocks(red, acc, kw, mw, lane, 0, 2);
        if (kw == 0) {
            #pragma unroll
            for (int half = 0; half < 2; half++) {
                int b = m0 + r + half * 8;
                float2 hv;
                #pragma unroll
                for (int j = 0; j < 2; j++) {
                    int col = 2 * c + j;
                    float gi = acc[0][half * 2 + j] + B0p[col];
                    float gg = acc[1][half * 2 + j] + B0p[8 + col];
                    float go = acc[2][half * 2 + j] + B0p[16 + col];
                    float si = 1.0f / (1.0f + expf(-gi));
                    float so = 1.0f / (1.0f + expf(-go));
                    (&hv.x)[j] = to_tf32(so * tanhf(si * tanhf(gg)));
                }
                *(float2*)&g_h0[b * HH + u0 + 2 * c] = hv;
            }
        }
        gridbar(&barno);

        // ---- P3: gates1 = h0 @ WP3^T (k=1024), act1 -> h ----
        #pragma unroll
        for (int blk = 0; blk < 3; blk++)
            #pragma unroll
            for (int q = 0; q < 4; q++) acc[blk][q] = 0.0f;
        run_phase<3>(smb, sm, g_h0, HH, WP3, HH, 512, 24, acc, tid, kw, m0, r, c);
        reduce_blocks(red, acc, kw, mw, lane, 0, 2);
        if (kw == 0) {
            #pragma unroll
            for (int half = 0; half < 2; half++) {
                int b = m0 + r + half * 8;
                float2 hv;
                #pragma unroll
                for (int j = 0; j < 2; j++) {
                    int col = 2 * c + j;
                    float gi = acc[0][half * 2 + j] + B1p[col];
                    float gg = acc[1][half * 2 + j] + B1p[8 + col];
                    float go = acc[2][half * 2 + j] + B1p[16 + col];
                    float si = 1.0f / (1.0f + expf(-gi));
                    float so = 1.0f / (1.0f + expf(-go));
                    (&hv.x)[j] = to_tf32(so * tanhf(si * tanhf(gg)));
                }
                *(float2*)&g_h[b * HH + u0 + 2 * c] = hv;
            }
        }
        gridbar(&barno);
    }
}

// ------------------------------- launch --------------------------------
extern "C" void kernel_launch(void* const* d_in, const int* in_sizes, int n_in,
                              void* d_out, int out_size) {
    const float* X    = (const float*)d_in[0];
    const float* Mm   = (const float*)d_in[1];
    const float* Wih0 = (const float*)d_in[2];
    const float* Whh0 = (const float*)d_in[3];
    const float* bih0 = (const float*)d_in[4];
    const float* bhh0 = (const float*)d_in[5];
    const float* Wih1 = (const float*)d_in[6];
    const float* Whh1 = (const float*)d_in[7];
    const float* bih1 = (const float*)d_in[8];
    const float* bhh1 = (const float*)d_in[9];
    const float* Wout = (const float*)d_in[10];
    const float* bout = (const float*)d_in[11];
    float* out = (float*)d_out;

    cudaFuncSetAttribute(rnn_persist, cudaFuncAttributeMaxDynamicSharedMemorySize,
                         SMEM_FLOATS * sizeof(float));

    pack_all<<<(PACK_TOT + 255) / 256, 256>>>(Wih0, Whh0, bih0, bhh0,
                                              Wih1, Whh1, bih1, bhh1, Wout);
    rnn_persist<<<NCTA, NTHR, SMEM_FLOATS * sizeof(float)>>>(X, Mm, bout, out);
}

// round 5
// speedup vs baseline: 1.1485x; 1.1485x over previous
#include <cuda_runtime.h>
#include <math.h>

#define BB 64
#define TT 128
#define DD 256
#define HH 1024
#define NCTA 128
#define NTHR 256
#define CH 64
#define SROW 68
#define STAGE_FLOATS (4*96*SROW)       // 26112
#define SMEM_FLOATS  (2*STAGE_FLOATS)  // 52224 floats = 208896 B

// ------------------------- device globals -------------------------
__device__ float g_WP1[NCTA*26*HH];   // per-CTA: 24 Whh0 i/g/o rows + 2 Wout rows (k-permuted)
__device__ float g_WP2[NCTA*24*DD];   // per-CTA Wih0 i/g/o rows (k-permuted)
__device__ float g_WP3[NCTA*24*HH];   // per-CTA (Wih1+Whh1) i/g/o rows (k-permuted)
__device__ float g_B0[NCTA*24];
__device__ float g_B1[NCTA*24];
__device__ float g_h[BB*HH];          // k-permuted within 8-groups
__device__ float g_h0[BB*HH];         // k-permuted
__device__ float g_imp[BB*DD];        // k-permuted
__device__ unsigned g_barcnt;

// ------------------------- helpers -------------------------
__device__ __forceinline__ float to_tf32(float x) {
    float y; asm("cvt.rna.tf32.f32 %0, %1;" : "=f"(y) : "f"(x)); return y;
}
__device__ __forceinline__ void mma_tf32(float* d, const unsigned* a, const unsigned* b) {
    asm volatile(
        "mma.sync.aligned.m16n8k8.row.col.f32.tf32.tf32.f32 "
        "{%0,%1,%2,%3},{%4,%5,%6,%7},{%8,%9},{%0,%1,%2,%3};"
        : "+f"(d[0]), "+f"(d[1]), "+f"(d[2]), "+f"(d[3])
        : "r"(a[0]), "r"(a[1]), "r"(a[2]), "r"(a[3]), "r"(b[0]), "r"(b[1]));
}
__device__ __forceinline__ void cpa16(unsigned s, const float* g) {
    asm volatile("cp.async.cg.shared.global [%0], [%1], 16;" :: "r"(s), "l"(g));
}
__device__ __forceinline__ void cpcommit() { asm volatile("cp.async.commit_group;"); }

// k-permutation within 8-groups: position p holds source k = finv(p)
__device__ __forceinline__ int fperm(int k7) { return ((k7 & 3) << 1) | (k7 >> 2); }
__device__ __forceinline__ int finv(int p7)  { return ((p7 & 1) << 2) | (p7 >> 1); }

// ------------------------- pack kernel -------------------------
__device__ __forceinline__ int phys_row(int cta, int r) {  // r in [0,24)
    int u = cta * 8 + (r & 7);
    int g = r >> 3;
    return u + (g == 0 ? 0 : (g == 1 ? 2048 : 3072));
}
#define N1 (NCTA*26*HH)
#define N2 (NCTA*24*DD)
#define N3 (NCTA*24*HH)
#define NBv (NCTA*24)
#define NHh (BB*HH)
#define PACK_TOT (N1+N2+N3+NBv+NHh)

__global__ void pack_all(const float* __restrict__ Wih0, const float* __restrict__ Whh0,
                         const float* __restrict__ bih0, const float* __restrict__ bhh0,
                         const float* __restrict__ Wih1, const float* __restrict__ Whh1,
                         const float* __restrict__ bih1, const float* __restrict__ bhh1,
                         const float* __restrict__ Wout) {
    int idx = blockIdx.x * 256 + threadIdx.x;
    if (idx < N1) {
        int cta = idx / 26624, rem = idx % 26624;
        int r = rem >> 10, kp = rem & 1023;
        int ks = (kp & ~7) | finv(kp & 7);
        float v;
        if (r < 24) v = Whh0[phys_row(cta, r) * HH + ks];
        else        v = Wout[(cta * 2 + (r - 24)) * HH + ks];
        g_WP1[idx] = to_tf32(v);
        return;
    }
    idx -= N1;
    if (idx < N2) {
        int cta = idx / 6144, rem = idx % 6144;
        int r = rem >> 8, kp = rem & 255;
        int ks = (kp & ~7) | finv(kp & 7);
        g_WP2[idx] = to_tf32(Wih0[phys_row(cta, r) * DD + ks]);
        return;
    }
    idx -= N2;
    if (idx < N3) {
        int cta = idx / 24576, rem = idx % 24576;
        int r = rem >> 10, kp = rem & 1023;
        int ks = (kp & ~7) | finv(kp & 7);
        int p = phys_row(cta, r);
        g_WP3[idx] = to_tf32(Wih1[p * HH + ks] + Whh1[p * HH + ks]);
        return;
    }
    idx -= N3;
    if (idx < NBv) {
        int p = phys_row(idx / 24, idx % 24);
        g_B0[idx] = bih0[p] + bhh0[p];
        g_B1[idx] = bih1[p] + bhh1[p];
        return;
    }
    idx -= NBv;
    if (idx < NHh) {
        g_h[idx] = 0.0f;
        if (idx == 0) g_barcnt = 0;
    }
}

// ------------------------- pipeline pieces -------------------------
// stage layout: [stage][kw 4][row 96][SROW]; A rows 0..63, W rows 64..64+R-1
template<int R>
__device__ __forceinline__ void load_stage(unsigned smb, int st,
        const float* __restrict__ A, int ldA,
        const float* __restrict__ W, int ldW,
        int KQ, int kbase, int tid) {
    const int seg = (tid & 15) << 2;       // 0..60
    const int v0  = tid >> 4;              // 0..15
    const unsigned sbase = smb + 4u * (st ? STAGE_FLOATS : 0);
    #pragma unroll
    for (int i = 0; i < 16; i++) {         // A: 4 kw x 64 rows x 16 segs
        int vk = v0 + (i << 4);            // 0..255
        int kw = vk >> 6, row = vk & 63;
        cpa16(sbase + 4u * ((kw * 96 + row) * SROW + seg),
              A + row * ldA + kw * KQ + kbase + seg);
    }
    #pragma unroll
    for (int i = 0; i < (R + 3) / 4; i++) {   // W: 4 kw x R rows x 16 segs
        int vk = v0 + (i << 4);
        if (vk < 4 * R) {
            int kw = vk / R, wrow = vk - kw * R;
            cpa16(sbase + 4u * ((kw * 96 + 64 + wrow) * SROW + seg),
                  W + wrow * ldW + kw * KQ + kbase + seg);
        }
    }
    cpcommit();
}

template<int NBLK>
__device__ __forceinline__ void compute_chunk(const float* sm, int st,
        int kw, int m0, int r, int c, float acc[2][4][4]) {
    const float* base = sm + (st ? STAGE_FLOATS : 0) + (kw * 96) * SROW;
    #pragma unroll
    for (int s = 0; s < 8; s++) {
        const int kb = s * 8 + 2 * c;      // permuted: pair = (k=c, k=c+4)
        float2 a0 = *(const float2*)&base[(m0 + r     ) * SROW + kb];
        float2 a1 = *(const float2*)&base[(m0 + r +  8) * SROW + kb];
        float2 a2 = *(const float2*)&base[(m0 + r + 16) * SROW + kb];
        float2 a3 = *(const float2*)&base[(m0 + r + 24) * SROW + kb];
        unsigned af0[4] = { __float_as_uint(a0.x), __float_as_uint(a1.x),
                            __float_as_uint(a0.y), __float_as_uint(a1.y) };
        unsigned af1[4] = { __float_as_uint(a2.x), __float_as_uint(a3.x),
                            __float_as_uint(a2.y), __float_as_uint(a3.y) };
        #pragma unroll
        for (int blk = 0; blk < NBLK; blk++) {
            float2 bv = *(const float2*)&base[(64 + blk * 8 + r) * SROW + kb];
            unsigned bf[2] = { __float_as_uint(bv.x), __float_as_uint(bv.y) };
            mma_tf32(acc[0][blk], af0, bf);
            mma_tf32(acc[1][blk], af1, bf);
        }
    }
}

template<int NBLK, int R>
__device__ __forceinline__ void run_phase(unsigned smb, const float* sm,
        const float* A, int ldA, const float* W, int ldW, int KQ,
        float acc[2][4][4], int tid, int kw, int m0, int r, int c) {
    const int nit = KQ / CH;
    load_stage<R>(smb, 0, A, ldA, W, ldW, KQ, 0, tid);
    for (int it = 0; it < nit; it++) {
        if (it + 1 < nit) {
            load_stage<R>(smb, (it + 1) & 1, A, ldA, W, ldW, KQ, (it + 1) * CH, tid);
            asm volatile("cp.async.wait_group 1;" ::: "memory");
        } else {
            asm volatile("cp.async.wait_group 0;" ::: "memory");
        }
        __syncthreads();
        compute_chunk<NBLK>(sm, it & 1, kw, m0, r, c, acc);
        __syncthreads();
    }
}

// 4-way kw reduce; scratch = ring base (free between phases). One sync.
__device__ __forceinline__ void reduce_acc(float* scr, float acc[2][4][4],
        int kw, int mw, int lane, int b0, int b1) {
    if (kw > 0) {
        float* p = scr + (((kw - 1) * 2 + mw) * 32 + lane) * 32;
        #pragma unroll
        for (int f = 0; f < 2; f++)
            for (int blk = b0; blk <= b1; blk++)
                *(float4*)&p[f * 16 + blk * 4] = *(const float4*)acc[f][blk];
    }
    __syncthreads();
    if (kw == 0) {
        #pragma unroll
        for (int g = 0; g < 3; g++) {
            const float* p = scr + ((g * 2 + mw) * 32 + lane) * 32;
            #pragma unroll
            for (int f = 0; f < 2; f++)
                for (int blk = b0; blk <= b1; blk++) {
                    float4 v = *(const float4*)&p[f * 16 + blk * 4];
                    acc[f][blk][0] += v.x; acc[f][blk][1] += v.y;
                    acc[f][blk][2] += v.z; acc[f][blk][3] += v.w;
                }
        }
    }
}

__device__ __forceinline__ void gridbar(unsigned* barno) {
    __syncthreads();
    (*barno)++;
    if (threadIdx.x == 0) {
        __threadfence();
        atomicAdd(&g_barcnt, 1u);
        unsigned target = (*barno) * NCTA, v;
        do {
            asm volatile("ld.acquire.gpu.global.u32 %0, [%1];" : "=r"(v) : "l"(&g_barcnt) : "memory");
        } while (v < target);
    }
    __syncthreads();
}

// ------------------------- persistent kernel -------------------------
__global__ void __launch_bounds__(NTHR, 1) rnn_persist(
        const float* __restrict__ X, const float* __restrict__ Mm,
        const float* __restrict__ bout, float* __restrict__ out) {
    extern __shared__ float sm[];
    unsigned smb = (unsigned)__cvta_generic_to_shared(sm);
    const int cta = blockIdx.x, tid = threadIdx.x;
    const int warp = tid >> 5, lane = tid & 31;
    const int kw = warp >> 1, mw = warp & 1;
    const int m0 = mw << 5, r = lane >> 2, c = lane & 3;
    const float* WP1 = g_WP1 + cta * 26 * HH;
    const float* WP2 = g_WP2 + cta * 24 * DD;
    const float* WP3 = g_WP3 + cta * 24 * HH;
    const float* B0p = g_B0 + cta * 24;
    const float* B1p = g_B1 + cta * 24;
    const int u0 = cta * 8, d0 = cta * 2;
    unsigned barno = 0;
    float acc[2][4][4];

    for (int t = 0;; t++) {
        if (t == TT) {   // h_final -> out tail (unpermute)
            for (int i = tid; i < 512; i += NTHR) {
                int gidx = cta * 512 + i;
                int b = gidx >> 10, u = gidx & 1023;
                out[BB * TT * DD + gidx] = g_h[b * HH + (u & ~7) + fperm(u & 7)];
            }
        }
        // ---- P1: [gates0-h | est(2 cols)] = h @ WP1^T (k=1024) ----
        #pragma unroll
        for (int f = 0; f < 2; f++)
            for (int blk = 0; blk < 4; blk++)
                for (int q = 0; q < 4; q++) acc[f][blk][q] = 0.0f;
        run_phase<4, 26>(smb, sm, g_h, HH, WP1, HH, 256, acc, tid, kw, m0, r, c);
        reduce_acc(sm, acc, kw, mw, lane, 3, 3);
        if (kw == 0 && c == 0) {    // est epilogue (cols 24,25)
            #pragma unroll
            for (int f = 0; f < 2; f++)
                for (int half = 0; half < 2; half++) {
                    int b = m0 + f * 16 + r + half * 8;
                    #pragma unroll
                    for (int j = 0; j < 2; j++) {
                        int d = d0 + j;
                        float e = acc[f][3][half * 2 + j] + bout[d];
                        if (t > 0) out[(b * TT + (t - 1)) * DD + d] = e;
                        if (t < TT) {
                            int xi = (b * TT + t) * DD + d;
                            float m = Mm[xi];
                            int pp = (d & ~7) | fperm(d & 7);
                            g_imp[b * DD + pp] = to_tf32(m * X[xi] + (1.0f - m) * e);
                        }
                    }
                }
        }
        if (t == TT) break;
        gridbar(&barno);

        // ---- P2: gates0 += imp @ WP2^T (k=256), act0 -> h0 ----
        run_phase<3, 24>(smb, sm, g_imp, DD, WP2, DD, 64, acc, tid, kw, m0, r, c);
        reduce_acc(sm, acc, kw, mw, lane, 0, 2);
        if (kw == 0) {
            #pragma unroll
            for (int j = 0; j < 2; j++) {
                int u = 2 * c + j;
                float bi = B0p[u], bg = B0p[8 + u], bo = B0p[16 + u];
                int up = u0 + fperm(u);
                #pragma unroll
                for (int f = 0; f < 2; f++)
                    for (int half = 0; half < 2; half++) {
                        int b = m0 + f * 16 + r + half * 8;
                        float gi = acc[f][0][half * 2 + j] + bi;
                        float gg = acc[f][1][half * 2 + j] + bg;
                        float go = acc[f][2][half * 2 + j] + bo;
                        float si = 1.0f / (1.0f + expf(-gi));
                        float so = 1.0f / (1.0f + expf(-go));
                        g_h0[b * HH + up] = to_tf32(so * tanhf(si * tanhf(gg)));
                    }
            }
        }
        gridbar(&barno);

        // ---- P3: gates1 = h0 @ WP3^T (k=1024), act1 -> h ----
        #pragma unroll
        for (int f = 0; f < 2; f++)
            for (int blk = 0; blk < 3; blk++)
                for (int q = 0; q < 4; q++) acc[f][blk][q] = 0.0f;
        run_phase<3, 24>(smb, sm, g_h0, HH, WP3, HH, 256, acc, tid, kw, m0, r, c);
        reduce_acc(sm, acc, kw, mw, lane, 0, 2);
        if (kw == 0) {
            #pragma unroll
            for (int j = 0; j < 2; j++) {
                int u = 2 * c + j;
                float bi = B1p[u], bg = B1p[8 + u], bo = B1p[16 + u];
                int up = u0 + fperm(u);
                #pragma unroll
                for (int f = 0; f < 2; f++)
                    for (int half = 0; half < 2; half++) {
                        int b = m0 + f * 16 + r + half * 8;
                        float gi = acc[f][0][half * 2 + j] + bi;
                        float gg = acc[f][1][half * 2 + j] + bg;
                        float go = acc[f][2][half * 2 + j] + bo;
                        float si = 1.0f / (1.0f + expf(-gi));
                        float so = 1.0f / (1.0f + expf(-go));
                        g_h[b * HH + up] = to_tf32(so * tanhf(si * tanhf(gg)));
                    }
            }
        }
        gridbar(&barno);
    }
}

// ------------------------------- launch --------------------------------
extern "C" void kernel_launch(void* const* d_in, const int* in_sizes, int n_in,
                              void* d_out, int out_size) {
    const float* X    = (const float*)d_in[0];
    const float* Mm   = (const float*)d_in[1];
    const float* Wih0 = (const float*)d_in[2];
    const float* Whh0 = (const float*)d_in[3];
    const float* bih0 = (const float*)d_in[4];
    const float* bhh0 = (const float*)d_in[5];
    const float* Wih1 = (const float*)d_in[6];
    const float* Whh1 = (const float*)d_in[7];
    const float* bih1 = (const float*)d_in[8];
    const float* bhh1 = (const float*)d_in[9];
    const float* Wout = (const float*)d_in[10];
    const float* bout = (const float*)d_in[11];
    float* out = (float*)d_out;

    cudaFuncSetAttribute(rnn_persist, cudaFuncAttributeMaxDynamicSharedMemorySize,
                         SMEM_FLOATS * sizeof(float));

    pack_all<<<(PACK_TOT + 255) / 256, 256>>>(Wih0, Whh0, bih0, bhh0,
                                              Wih1, Whh1, bih1, bhh1, Wout);
    rnn_persist<<<NCTA, NTHR, SMEM_FLOATS * sizeof(float)>>>(X, Mm, bout, out);
}

// round 6
// speedup vs baseline: 1.4387x; 1.2527x over previous
#include <cuda_runtime.h>
#include <math.h>

#define BB 64
#define TT 128
#define DD 256
#define HH 1024
#define NCTA 128
#define NTHR 256
#define CH 64
#define SROW 68
#define STAGE_FLOATS (2*96*SROW)       // 13056 floats per stage (2 kw x 96 rows)
#define RED_OFF (3*STAGE_FLOATS)       // 39168
#define SMEM_FLOATS (RED_OFF + 2048)   // 41216 floats = 164864 B

// ------------------------- device globals -------------------------
__device__ float g_WP1[NCTA*26*HH];   // per-CTA: 24 Whh0 i/g/o rows + 2 Wout rows
__device__ float g_WP2[NCTA*24*DD];   // per-CTA Wih0 i/g/o rows
__device__ float g_WP3[NCTA*24*HH];   // per-CTA (Wih1+Whh1) i/g/o rows
__device__ float g_B0[NCTA*24];
__device__ float g_B1[NCTA*24];
__device__ float g_h[BB*HH];
__device__ float g_h0[BB*HH];
__device__ float g_imp[BB*DD];
__device__ unsigned g_barcnt;

// ------------------------- helpers -------------------------
__device__ __forceinline__ float to_tf32(float x) {
    float y; asm("cvt.rna.tf32.f32 %0, %1;" : "=f"(y) : "f"(x)); return y;
}
__device__ __forceinline__ void mma_tf32(float* d, const unsigned* a, const unsigned* b) {
    asm volatile(
        "mma.sync.aligned.m16n8k8.row.col.f32.tf32.tf32.f32 "
        "{%0,%1,%2,%3},{%4,%5,%6,%7},{%8,%9},{%0,%1,%2,%3};"
        : "+f"(d[0]), "+f"(d[1]), "+f"(d[2]), "+f"(d[3])
        : "r"(a[0]), "r"(a[1]), "r"(a[2]), "r"(a[3]), "r"(b[0]), "r"(b[1]));
}
__device__ __forceinline__ void cpa16(unsigned s, const float* g) {
    asm volatile("cp.async.cg.shared.global [%0], [%1], 16;" :: "r"(s), "l"(g));
}
__device__ __forceinline__ void cpcommit() { asm volatile("cp.async.commit_group;"); }

__device__ __forceinline__ int As_idx(int st, int kw, int row, int k) {
    return st * STAGE_FLOATS + (kw * 96 + row) * SROW + k;
}
__device__ __forceinline__ int Ws_idx(int st, int kw, int row, int k) {
    return st * STAGE_FLOATS + (kw * 96 + 64 + row) * SROW + k;
}

// ------------------------- pack kernel -------------------------
__device__ __forceinline__ int phys_row(int cta, int r) {  // r in [0,24)
    int u = cta * 8 + (r & 7);
    int g = r >> 3;
    return u + (g == 0 ? 0 : (g == 1 ? 2048 : 3072));
}
#define N1 (NCTA*26*HH)
#define N2 (NCTA*24*DD)
#define N3 (NCTA*24*HH)
#define NBv (NCTA*24)
#define NHh (BB*HH)
#define PACK_TOT (N1+N2+N3+NBv+NHh)

__global__ void pack_all(const float* __restrict__ Wih0, const float* __restrict__ Whh0,
                         const float* __restrict__ bih0, const float* __restrict__ bhh0,
                         const float* __restrict__ Wih1, const float* __restrict__ Whh1,
                         const float* __restrict__ bih1, const float* __restrict__ bhh1,
                         const float* __restrict__ Wout) {
    int idx = blockIdx.x * 256 + threadIdx.x;
    if (idx < N1) {
        int cta = idx / 26624, rem = idx % 26624;
        int r = rem >> 10, k = rem & 1023;
        float v;
        if (r < 24) v = Whh0[phys_row(cta, r) * HH + k];
        else        v = Wout[(cta * 2 + (r - 24)) * HH + k];
        g_WP1[idx] = to_tf32(v);
        return;
    }
    idx -= N1;
    if (idx < N2) {
        int cta = idx / 6144, rem = idx % 6144;
        int r = rem >> 8, k = rem & 255;
        g_WP2[idx] = to_tf32(Wih0[phys_row(cta, r) * DD + k]);
        return;
    }
    idx -= N2;
    if (idx < N3) {
        int cta = idx / 24576, rem = idx % 24576;
        int r = rem >> 10, k = rem & 1023;
        int p = phys_row(cta, r);
        g_WP3[idx] = to_tf32(Wih1[p * HH + k] + Whh1[p * HH + k]);
        return;
    }
    idx -= N3;
    if (idx < NBv) {
        int p = phys_row(idx / 24, idx % 24);
        g_B0[idx] = bih0[p] + bhh0[p];
        g_B1[idx] = bih1[p] + bhh1[p];
        return;
    }
    idx -= NBv;
    if (idx < NHh) {
        g_h[idx] = 0.0f;
        if (idx == 0) g_barcnt = 0;
    }
}

// ------------------------- pipeline pieces -------------------------
template<int R>
__device__ __forceinline__ void load_stage(unsigned smb, int st,
        const float* __restrict__ A, int ldA,
        const float* __restrict__ W, int ldW,
        int khalf, int kbase, int tid) {
    // A: 2 kw x 64 rows x 16 segs = 2048 slots
    #pragma unroll
    for (int i = 0; i < 8; i++) {
        int u = tid + i * NTHR;
        int kw = u >> 10, v = u & 1023;
        int row = v >> 4, seg = (v & 15) << 2;
        cpa16(smb + 4u * As_idx(st, kw, row, seg),
              A + row * ldA + kw * khalf + kbase + seg);
    }
    // W: 2 kw x 32 rows x 16 segs = 1024 slots (guard row<R)
    #pragma unroll
    for (int i = 0; i < 4; i++) {
        int u = tid + i * NTHR;
        int kw = u >> 9, v = u & 511;
        int row = v >> 4, seg = (v & 15) << 2;
        if (row < R)
            cpa16(smb + 4u * Ws_idx(st, kw, row, seg),
                  W + row * ldW + kw * khalf + kbase + seg);
    }
    cpcommit();
}

template<int NBLK>
__device__ __forceinline__ void compute_chunk(const float* sm, int st,
        int kw, int m0, int r, int c, float acc[4][4]) {
    #pragma unroll
    for (int s = 0; s < 8; s++) {
        int kb = s * 8;
        unsigned a[4];
        a[0] = __float_as_uint(sm[As_idx(st, kw, m0 + r,     kb + c)]);
        a[1] = __float_as_uint(sm[As_idx(st, kw, m0 + r + 8, kb + c)]);
        a[2] = __float_as_uint(sm[As_idx(st, kw, m0 + r,     kb + c + 4)]);
        a[3] = __float_as_uint(sm[As_idx(st, kw, m0 + r + 8, kb + c + 4)]);
        #pragma unroll
        for (int blk = 0; blk < NBLK; blk++) {
            unsigned b[2];
            b[0] = __float_as_uint(sm[Ws_idx(st, kw, blk * 8 + r, kb + c)]);
            b[1] = __float_as_uint(sm[Ws_idx(st, kw, blk * 8 + r, kb + c + 4)]);
            mma_tf32(acc[blk], a, b);
        }
    }
}

// 3-stage ring, depth-2 prefetch, ONE sync per chunk.
// Per iter: wait(group it done) -> sync -> issue load(it+2) -> compute(it).
template<int NBLK, int R>
__device__ __forceinline__ void run_phase(unsigned smb, const float* sm,
        const float* A, int ldA, const float* W, int ldW, int khalf,
        float acc[4][4], int tid, int kw, int m0, int r, int c) {
    const int nit = khalf / CH;
    load_stage<R>(smb, 0, A, ldA, W, ldW, khalf, 0, tid);
    load_stage<R>(smb, 1, A, ldA, W, ldW, khalf, CH, tid);
    int st = 0;
    for (int it = 0; it < nit; it++) {
        if (it + 1 < nit)
            asm volatile("cp.async.wait_group 1;" ::: "memory");
        else
            asm volatile("cp.async.wait_group 0;" ::: "memory");
        __syncthreads();
        if (it + 2 < nit) {
            int slot = st + 2; if (slot >= 3) slot -= 3;
            load_stage<R>(smb, slot, A, ldA, W, ldW, khalf, (it + 2) * CH, tid);
        }
        compute_chunk<NBLK>(sm, st, kw, m0, r, c, acc);
        if (++st == 3) st = 0;
    }
}

// single-sync cross-kw reduction; scratch at RED_OFF (fenced by phase syncs)
__device__ __forceinline__ void reduce_blocks(float* red, float acc[4][4],
        int kw, int mw, int lane, int b0, int b1) {
    if (kw == 1)
        for (int blk = b0; blk <= b1; blk++)
            #pragma unroll
            for (int q = 0; q < 4; q++)
                red[((mw * 4 + blk) * 32 + lane) * 4 + q] = acc[blk][q];
    __syncthreads();
    if (kw == 0)
        for (int blk = b0; blk <= b1; blk++)
            #pragma unroll
            for (int q = 0; q < 4; q++)
                acc[blk][q] += red[((mw * 4 + blk) * 32 + lane) * 4 + q];
}

__device__ __forceinline__ void gridbar(unsigned* barno) {
    __syncthreads();
    (*barno)++;
    if (threadIdx.x == 0) {
        __threadfence();
        atomicAdd(&g_barcnt, 1u);
        unsigned target = (*barno) * NCTA, v;
        do {
            asm volatile("ld.acquire.gpu.global.u32 %0, [%1];" : "=r"(v) : "l"(&g_barcnt) : "memory");
        } while (v < target);
    }
    __syncthreads();
}

// ------------------------- persistent kernel -------------------------
__global__ void __launch_bounds__(NTHR, 1) rnn_persist(
        const float* __restrict__ X, const float* __restrict__ Mm,
        const float* __restrict__ bout, float* __restrict__ out) {
    extern __shared__ float sm[];
    unsigned smb = (unsigned)__cvta_generic_to_shared(sm);
    float* red = sm + RED_OFF;
    const int cta = blockIdx.x, tid = threadIdx.x;
    const int warp = tid >> 5, lane = tid & 31;
    const int mw = warp & 3, kw = warp >> 2;
    const int m0 = mw << 4, r = lane >> 2, c = lane & 3;
    const float* WP1 = g_WP1 + cta * 26 * HH;
    const float* WP2 = g_WP2 + cta * 24 * DD;
    const float* WP3 = g_WP3 + cta * 24 * HH;
    const float* B0p = g_B0 + cta * 24;
    const float* B1p = g_B1 + cta * 24;
    const int u0 = cta * 8, d0 = cta * 2;
    unsigned barno = 0;
    float acc[4][4];

    // zero the W pad rows (26..31) of every stage/kw once; loads never touch them
    for (int i = tid; i < 3 * 2 * 6 * SROW; i += NTHR) {
        int st = i / (2 * 6 * SROW), rem = i % (2 * 6 * SROW);
        int kwz = rem / (6 * SROW), rem2 = rem % (6 * SROW);
        sm[Ws_idx(st, kwz, 26 + rem2 / SROW, rem2 % SROW)] = 0.0f;
    }
    __syncthreads();

    for (int t = 0;; t++) {
        if (t == TT) {   // h_final -> out tail
            for (int i = tid; i < 512; i += NTHR)
                out[BB * TT * DD + cta * 512 + i] = g_h[cta * 512 + i];
        }
        // ---- P1: [gates0-h (24) | est (2, in block 3)] = h @ WP1^T (k=1024) ----
        #pragma unroll
        for (int blk = 0; blk < 4; blk++)
            #pragma unroll
            for (int q = 0; q < 4; q++) acc[blk][q] = 0.0f;
        run_phase<4, 26>(smb, sm, g_h, HH, WP1, HH, 512, acc, tid, kw, m0, r, c);
        reduce_blocks(red, acc, kw, mw, lane, 3, 3);
        if (kw == 0 && c == 0) {   // est epilogue: cols 0,1 of block 3
            #pragma unroll
            for (int half = 0; half < 2; half++) {
                int b = m0 + r + half * 8;
                #pragma unroll
                for (int j = 0; j < 2; j++) {
                    int d = d0 + j;
                    float e = acc[3][half * 2 + j] + bout[d];
                    if (t > 0) out[(b * TT + (t - 1)) * DD + d] = e;
                    if (t < TT) {
                        int xi = (b * TT + t) * DD + d;
                        float m = Mm[xi];
                        g_imp[b * DD + d] = to_tf32(m * X[xi] + (1.0f - m) * e);
                    }
                }
            }
        }
        if (t == TT) break;
        gridbar(&barno);

        // ---- P2: gates0 += imp @ WP2^T (k=256), act0 -> h0 ----
        run_phase<3, 24>(smb, sm, g_imp, DD, WP2, DD, 128, acc, tid, kw, m0, r, c);
        reduce_blocks(red, acc, kw, mw, lane, 0, 2);
        if (kw == 0) {
            #pragma unroll
            for (int half = 0; half < 2; half++) {
                int b = m0 + r + half * 8;
                float2 hv;
                #pragma unroll
                for (int j = 0; j < 2; j++) {
                    int col = 2 * c + j;
                    float gi = acc[0][half * 2 + j] + B0p[col];
                    float gg = acc[1][half * 2 + j] + B0p[8 + col];
                    float go = acc[2][half * 2 + j] + B0p[16 + col];
                    float si = 1.0f / (1.0f + expf(-gi));
                    float so = 1.0f / (1.0f + expf(-go));
                    (&hv.x)[j] = to_tf32(so * tanhf(si * tanhf(gg)));
                }
                *(float2*)&g_h0[b * HH + u0 + 2 * c] = hv;
            }
        }
        gridbar(&barno);

        // ---- P3: gates1 = h0 @ WP3^T (k=1024), act1 -> h ----
        #pragma unroll
        for (int blk = 0; blk < 3; blk++)
            #pragma unroll
            for (int q = 0; q < 4; q++) acc[blk][q] = 0.0f;
        run_phase<3, 24>(smb, sm, g_h0, HH, WP3, HH, 512, acc, tid, kw, m0, r, c);
        reduce_blocks(red, acc, kw, mw, lane, 0, 2);
        if (kw == 0) {
            #pragma unroll
            for (int half = 0; half < 2; half++) {
                int b = m0 + r + half * 8;
                float2 hv;
                #pragma unroll
                for (int j = 0; j < 2; j++) {
                    int col = 2 * c + j;
                    float gi = acc[0][half * 2 + j] + B1p[col];
                    float gg = acc[1][half * 2 + j] + B1p[8 + col];
                    float go = acc[2][half * 2 + j] + B1p[16 + col];
                    float si = 1.0f / (1.0f + expf(-gi));
                    float so = 1.0f / (1.0f + expf(-go));
                    (&hv.x)[j] = to_tf32(so * tanhf(si * tanhf(gg)));
                }
                *(float2*)&g_h[b * HH + u0 + 2 * c] = hv;
            }
        }
        gridbar(&barno);
    }
}

// ------------------------------- launch --------------------------------
extern "C" void kernel_launch(void* const* d_in, const int* in_sizes, int n_in,
                              void* d_out, int out_size) {
    const float* X    = (const float*)d_in[0];
    const float* Mm   = (const float*)d_in[1];
    const float* Wih0 = (const float*)d_in[2];
    const float* Whh0 = (const float*)d_in[3];
    const float* bih0 = (const float*)d_in[4];
    const float* bhh0 = (const float*)d_in[5];
    const float* Wih1 = (const float*)d_in[6];
    const float* Whh1 = (const float*)d_in[7];
    const float* bih1 = (const float*)d_in[8];
    const float* bhh1 = (const float*)d_in[9];
    const float* Wout = (const float*)d_in[10];
    const float* bout = (const float*)d_in[11];
    float* out = (float*)d_out;

    cudaFuncSetAttribute(rnn_persist, cudaFuncAttributeMaxDynamicSharedMemorySize,
                         SMEM_FLOATS * sizeof(float));

    pack_all<<<(PACK_TOT + 255) / 256, 256>>>(Wih0, Whh0, bih0, bhh0,
                                              Wih1, Whh1, bih1, bhh1, Wout);
    rnn_persist<<<NCTA, NTHR, SMEM_FLOATS * sizeof(float)>>>(X, Mm, bout, out);
}

// round 7
// speedup vs baseline: 2.1520x; 1.4958x over previous
#include <cuda_runtime.h>
#include <cuda_fp16.h>
#include <math.h>

#define BB 64
#define TT 128
#define DD 256
#define HH 1024
#define NCTA 128
#define NTHR 256
#define CH 64                    // k-chunk (halves) per kw per stage
#define SROW_H 72                // smem row stride in halves (144B, conflict-free)
#define STAGE_H (2*96*SROW_H)    // 13824 halves per stage
#define RED_BYTE_OFF (3*STAGE_H*2)          // 82944 B
#define SMEM_BYTES (RED_BYTE_OFF + 2048*4)  // + 8KB fp32 reduce scratch

// ------------------------- device globals -------------------------
__device__ __half g_WP1[NCTA*26*HH];  // per-CTA: 24 Whh0 i/g/o rows + 2 Wout rows
__device__ __half g_WP2[NCTA*24*DD];  // per-CTA Wih0 i/g/o rows
__device__ __half g_WP3[NCTA*24*HH];  // per-CTA (Wih1+Whh1) i/g/o rows
__device__ float  g_B0[NCTA*24];
__device__ float  g_B1[NCTA*24];
__device__ __half g_h[BB*HH];
__device__ __half g_h0[BB*HH];
__device__ __half g_imp[BB*DD];
__device__ float  g_hf[BB*HH];        // fp32 h_final (written at t==TT-1)
__device__ unsigned g_barcnt;

// ------------------------- helpers -------------------------
__device__ __forceinline__ void mma_f16(float* d, const unsigned* a, const unsigned* b) {
    asm volatile(
        "mma.sync.aligned.m16n8k16.row.col.f32.f16.f16.f32 "
        "{%0,%1,%2,%3},{%4,%5,%6,%7},{%8,%9},{%0,%1,%2,%3};"
        : "+f"(d[0]), "+f"(d[1]), "+f"(d[2]), "+f"(d[3])
        : "r"(a[0]), "r"(a[1]), "r"(a[2]), "r"(a[3]), "r"(b[0]), "r"(b[1]));
}
__device__ __forceinline__ void cpa16(unsigned s, const void* g) {
    asm volatile("cp.async.cg.shared.global [%0], [%1], 16;" :: "r"(s), "l"(g));
}
__device__ __forceinline__ void cpcommit() { asm volatile("cp.async.commit_group;"); }

__device__ __forceinline__ int As_idx(int st, int kw, int row, int k) {   // halves
    return st * STAGE_H + (kw * 96 + row) * SROW_H + k;
}
__device__ __forceinline__ int Ws_idx(int st, int kw, int row, int k) {
    return st * STAGE_H + (kw * 96 + 64 + row) * SROW_H + k;
}

// ------------------------- pack kernel -------------------------
__device__ __forceinline__ int phys_row(int cta, int r) {  // r in [0,24)
    int u = cta * 8 + (r & 7);
    int g = r >> 3;
    return u + (g == 0 ? 0 : (g == 1 ? 2048 : 3072));
}
#define N1 (NCTA*26*HH)
#define N2 (NCTA*24*DD)
#define N3 (NCTA*24*HH)
#define NBv (NCTA*24)
#define NHh (BB*HH)
#define PACK_TOT (N1+N2+N3+NBv+NHh)

__global__ void pack_all(const float* __restrict__ Wih0, const float* __restrict__ Whh0,
                         const float* __restrict__ bih0, const float* __restrict__ bhh0,
                         const float* __restrict__ Wih1, const float* __restrict__ Whh1,
                         const float* __restrict__ bih1, const float* __restrict__ bhh1,
                         const float* __restrict__ Wout) {
    int idx = blockIdx.x * 256 + threadIdx.x;
    if (idx < N1) {
        int cta = idx / 26624, rem = idx % 26624;
        int r = rem >> 10, k = rem & 1023;
        float v;
        if (r < 24) v = Whh0[phys_row(cta, r) * HH + k];
        else        v = Wout[(cta * 2 + (r - 24)) * HH + k];
        g_WP1[idx] = __float2half_rn(v);
        return;
    }
    idx -= N1;
    if (idx < N2) {
        int cta = idx / 6144, rem = idx % 6144;
        int r = rem >> 8, k = rem & 255;
        g_WP2[idx] = __float2half_rn(Wih0[phys_row(cta, r) * DD + k]);
        return;
    }
    idx -= N2;
    if (idx < N3) {
        int cta = idx / 24576, rem = idx % 24576;
        int r = rem >> 10, k = rem & 1023;
        int p = phys_row(cta, r);
        g_WP3[idx] = __float2half_rn(Wih1[p * HH + k] + Whh1[p * HH + k]);
        return;
    }
    idx -= N3;
    if (idx < NBv) {
        int p = phys_row(idx / 24, idx % 24);
        g_B0[idx] = bih0[p] + bhh0[p];
        g_B1[idx] = bih1[p] + bhh1[p];
        return;
    }
    idx -= NBv;
    if (idx < NHh) {
        g_h[idx] = __float2half_rn(0.0f);
        if (idx == 0) g_barcnt = 0;
    }
}

// ------------------------- pipeline pieces -------------------------
template<int R>
__device__ __forceinline__ void load_stage(unsigned smb, int st,
        const __half* __restrict__ A, int ldA,
        const __half* __restrict__ W, int ldW,
        int khalf, int kbase, int tid) {
    // A: 2 kw x 64 rows x 8 segs(16B) = 1024 slots
    #pragma unroll
    for (int i = 0; i < 4; i++) {
        int u = tid + i * NTHR;
        int kw = u >> 9, v = u & 511;
        int row = v >> 3, seg = (v & 7) << 3;   // seg in halves
        cpa16(smb + 2u * As_idx(st, kw, row, seg),
              A + row * ldA + kw * khalf + kbase + seg);
    }
    // W: 2 kw x 32 rows x 8 segs = 512 slots (guard row<R)
    #pragma unroll
    for (int i = 0; i < 2; i++) {
        int u = tid + i * NTHR;
        int kw = u >> 8, v = u & 255;
        int row = v >> 3, seg = (v & 7) << 3;
        if (row < R)
            cpa16(smb + 2u * Ws_idx(st, kw, row, seg),
                  W + row * ldW + kw * khalf + kbase + seg);
    }
    cpcommit();
}

template<int NBLK>
__device__ __forceinline__ void compute_chunk(const __half* sm, int st,
        int kw, int m0, int r, int c, float acc[4][4]) {
    #pragma unroll
    for (int s = 0; s < 4; s++) {
        int kb = s * 16;
        unsigned a[4];
        a[0] = *(const unsigned*)&sm[As_idx(st, kw, m0 + r,     kb + 2*c)];
        a[1] = *(const unsigned*)&sm[As_idx(st, kw, m0 + r + 8, kb + 2*c)];
        a[2] = *(const unsigned*)&sm[As_idx(st, kw, m0 + r,     kb + 2*c + 8)];
        a[3] = *(const unsigned*)&sm[As_idx(st, kw, m0 + r + 8, kb + 2*c + 8)];
        #pragma unroll
        for (int blk = 0; blk < NBLK; blk++) {
            unsigned b[2];
            b[0] = *(const unsigned*)&sm[Ws_idx(st, kw, blk * 8 + r, kb + 2*c)];
            b[1] = *(const unsigned*)&sm[Ws_idx(st, kw, blk * 8 + r, kb + 2*c + 8)];
            mma_f16(acc[blk], a, b);
        }
    }
}

// 3-stage ring, depth-2 prefetch, ONE sync per chunk.
template<int NBLK, int R>
__device__ __forceinline__ void run_phase(unsigned smb, const __half* sm,
        const __half* A, int ldA, const __half* W, int ldW, int khalf,
        float acc[4][4], int tid, int kw, int m0, int r, int c) {
    const int nit = khalf / CH;
    load_stage<R>(smb, 0, A, ldA, W, ldW, khalf, 0, tid);
    load_stage<R>(smb, 1, A, ldA, W, ldW, khalf, CH, tid);
    int st = 0;
    for (int it = 0; it < nit; it++) {
        if (it + 1 < nit)
            asm volatile("cp.async.wait_group 1;" ::: "memory");
        else
            asm volatile("cp.async.wait_group 0;" ::: "memory");
        __syncthreads();
        if (it + 2 < nit) {
            int slot = st + 2; if (slot >= 3) slot -= 3;
            load_stage<R>(smb, slot, A, ldA, W, ldW, khalf, (it + 2) * CH, tid);
        }
        compute_chunk<NBLK>(sm, st, kw, m0, r, c, acc);
        if (++st == 3) st = 0;
    }
}

__device__ __forceinline__ void reduce_blocks(float* red, float acc[4][4],
        int kw, int mw, int lane, int b0, int b1) {
    if (kw == 1)
        for (int blk = b0; blk <= b1; blk++)
            #pragma unroll
            for (int q = 0; q < 4; q++)
                red[((mw * 4 + blk) * 32 + lane) * 4 + q] = acc[blk][q];
    __syncthreads();
    if (kw == 0)
        for (int blk = b0; blk <= b1; blk++)
            #pragma unroll
            for (int q = 0; q < 4; q++)
                acc[blk][q] += red[((mw * 4 + blk) * 32 + lane) * 4 + q];
}

__device__ __forceinline__ void gridbar(unsigned* barno) {
    __syncthreads();
    (*barno)++;
    if (threadIdx.x == 0) {
        __threadfence();
        atomicAdd(&g_barcnt, 1u);
        unsigned target = (*barno) * NCTA, v;
        do {
            asm volatile("ld.acquire.gpu.global.u32 %0, [%1];" : "=r"(v) : "l"(&g_barcnt) : "memory");
        } while (v < target);
    }
    __syncthreads();
}

// ------------------------- persistent kernel -------------------------
__global__ void __launch_bounds__(NTHR, 1) rnn_persist(
        const float* __restrict__ X, const float* __restrict__ Mm,
        const float* __restrict__ bout, float* __restrict__ out) {
    extern __shared__ char smraw[];
    __half* sm = (__half*)smraw;
    float* red = (float*)(smraw + RED_BYTE_OFF);
    unsigned smb = (unsigned)__cvta_generic_to_shared(smraw);
    const int cta = blockIdx.x, tid = threadIdx.x;
    const int warp = tid >> 5, lane = tid & 31;
    const int mw = warp & 3, kw = warp >> 2;
    const int m0 = mw << 4, r = lane >> 2, c = lane & 3;
    const __half* WP1 = g_WP1 + cta * 26 * HH;
    const __half* WP2 = g_WP2 + cta * 24 * DD;
    const __half* WP3 = g_WP3 + cta * 24 * HH;
    const float* B0p = g_B0 + cta * 24;
    const float* B1p = g_B1 + cta * 24;
    const int u0 = cta * 8, d0 = cta * 2;
    unsigned barno = 0;
    float acc[4][4];

    // zero the W pad rows (26..31) of every stage/kw once
    for (int i = tid; i < 3 * 2 * 6 * SROW_H; i += NTHR) {
        int st = i / (2 * 6 * SROW_H), rem = i % (2 * 6 * SROW_H);
        int kwz = rem / (6 * SROW_H), rem2 = rem % (6 * SROW_H);
        sm[Ws_idx(st, kwz, 26 + rem2 / SROW_H, rem2 % SROW_H)] = __float2half_rn(0.0f);
    }
    __syncthreads();

    for (int t = 0;; t++) {
        if (t == TT) {   // h_final -> out tail (fp32 copy)
            for (int i = tid; i < 512; i += NTHR)
                out[BB * TT * DD + cta * 512 + i] = g_hf[cta * 512 + i];
        }
        // ---- P1: [gates0-h (24) | est (2, block 3)] = h @ WP1^T (k=1024) ----
        #pragma unroll
        for (int blk = 0; blk < 4; blk++)
            #pragma unroll
            for (int q = 0; q < 4; q++) acc[blk][q] = 0.0f;
        run_phase<4, 26>(smb, sm, g_h, HH, WP1, HH, 512, acc, tid, kw, m0, r, c);
        reduce_blocks(red, acc, kw, mw, lane, 3, 3);
        if (kw == 0 && c == 0) {   // est epilogue: cols 0,1 of block 3
            #pragma unroll
            for (int half = 0; half < 2; half++) {
                int b = m0 + r + half * 8;
                float ev[2];
                #pragma unroll
                for (int j = 0; j < 2; j++) {
                    int d = d0 + j;
                    float e = acc[3][half * 2 + j] + bout[d];
                    if (t > 0) out[(b * TT + (t - 1)) * DD + d] = e;
                    if (t < TT) {
                        int xi = (b * TT + t) * DD + d;
                        float m = Mm[xi];
                        ev[j] = m * X[xi] + (1.0f - m) * e;
                    }
                }
                if (t < TT)
                    *(__half2*)&g_imp[b * DD + d0] = __floats2half2_rn(ev[0], ev[1]);
            }
        }
        if (t == TT) break;
        gridbar(&barno);

        // ---- P2: gates0 += imp @ WP2^T (k=256), act0 -> h0 ----
        run_phase<3, 24>(smb, sm, g_imp, DD, WP2, DD, 128, acc, tid, kw, m0, r, c);
        reduce_blocks(red, acc, kw, mw, lane, 0, 2);
        if (kw == 0) {
            #pragma unroll
            for (int half = 0; half < 2; half++) {
                int b = m0 + r + half * 8;
                float hv[2];
                #pragma unroll
                for (int j = 0; j < 2; j++) {
                    int col = 2 * c + j;
                    float gi = acc[0][half * 2 + j] + B0p[col];
                    float gg = acc[1][half * 2 + j] + B0p[8 + col];
                    float go = acc[2][half * 2 + j] + B0p[16 + col];
                    float si = 1.0f / (1.0f + expf(-gi));
                    float so = 1.0f / (1.0f + expf(-go));
                    hv[j] = so * tanhf(si * tanhf(gg));
                }
                *(__half2*)&g_h0[b * HH + u0 + 2 * c] = __floats2half2_rn(hv[0], hv[1]);
            }
        }
        gridbar(&barno);

        // ---- P3: gates1 = h0 @ WP3^T (k=1024), act1 -> h ----
        #pragma unroll
        for (int blk = 0; blk < 3; blk++)
            #pragma unroll
            for (int q = 0; q < 4; q++) acc[blk][q] = 0.0f;
        run_phase<3, 24>(smb, sm, g_h0, HH, WP3, HH, 512, acc, tid, kw, m0, r, c);
        reduce_blocks(red, acc, kw, mw, lane, 0, 2);
        if (kw == 0) {
            #pragma unroll
            for (int half = 0; half < 2; half++) {
                int b = m0 + r + half * 8;
                float hv[2];
                #pragma unroll
                for (int j = 0; j < 2; j++) {
                    int col = 2 * c + j;
                    float gi = acc[0][half * 2 + j] + B1p[col];
                    float gg = acc[1][half * 2 + j] + B1p[8 + col];
                    float go = acc[2][half * 2 + j] + B1p[16 + col];
                    float si = 1.0f / (1.0f + expf(-gi));
                    float so = 1.0f / (1.0f + expf(-go));
                    hv[j] = so * tanhf(si * tanhf(gg));
                }
                *(__half2*)&g_h[b * HH + u0 + 2 * c] = __floats2half2_rn(hv[0], hv[1]);
                if (t == TT - 1)
                    *(float2*)&g_hf[b * HH + u0 + 2 * c] = make_float2(hv[0], hv[1]);
            }
        }
        gridbar(&barno);
    }
}

// ------------------------------- launch --------------------------------
extern "C" void kernel_launch(void* const* d_in, const int* in_sizes, int n_in,
                              void* d_out, int out_size) {
    const float* X    = (const float*)d_in[0];
    const float* Mm   = (const float*)d_in[1];
    const float* Wih0 = (const float*)d_in[2];
    const float* Whh0 = (const float*)d_in[3];
    const float* bih0 = (const float*)d_in[4];
    const float* bhh0 = (const float*)d_in[5];
    const float* Wih1 = (const float*)d_in[6];
    const float* Whh1 = (const float*)d_in[7];
    const float* bih1 = (const float*)d_in[8];
    const float* bhh1 = (const float*)d_in[9];
    const float* Wout = (const float*)d_in[10];
    const float* bout = (const float*)d_in[11];
    float* out = (float*)d_out;

    cudaFuncSetAttribute(rnn_persist, cudaFuncAttributeMaxDynamicSharedMemorySize,
                         SMEM_BYTES);

    pack_all<<<(PACK_TOT + 255) / 256, 256>>>(Wih0, Whh0, bih0, bhh0,
                                              Wih1, Whh1, bih1, bhh1, Wout);
    rnn_persist<<<NCTA, NTHR, SMEM_BYTES>>>(X, Mm, bout, out);
}